// round 14
// baseline (speedup 1.0000x reference)
#include <cuda_runtime.h>
#include <cuda_bf16.h>
#include <mma.h>
#include <cstdint>
#include <math.h>

using namespace nvcuda;

#define NR 8192
#define DD 512
#define BATCH 2048
#define NCLS 200

// ---------------- scratch (__device__ globals, no allocation) ----------------
__device__ signed char g_q[(size_t)NR * DD];     // quantized normalized features (4 MB)
__device__ float g_rows[(size_t)NR * 8];         // per-row {T,P,Q,R,Pv,Qv,Rv,pad} (256 KB)
__device__ int g_chist[NCLS];
__device__ double g_ce;
__device__ unsigned g_done;
__device__ unsigned g_ready;
__device__ unsigned char g_tcls[BATCH];

// ---------------- fused decode + normalize(+quantize) + CE + zeroing ----------------
// block 0: decode targets (dtype-agnostic) + histogram + reset flags, then set ready
// blocks 1..1024: 8 rows each, one warp per row (normalize+quantize)
// blocks 1025..1280: 8 CE samples each, one warp per sample (spin on ready for g_tcls)
// blocks 1281..1296: zero g_rows slices
#define NORM_BLKS (NR / 8)          // 1024
#define CE_BLKS (BATCH / 8)         // 256
#define ZBLK 16
#define NC_GRID (1 + NORM_BLKS + CE_BLKS + ZBLK)

__global__ void __launch_bounds__(256) norm_ce_kernel(const float* __restrict__ x,
                                                      const float* __restrict__ pred,
                                                      const unsigned int* __restrict__ traw) {
    const int b = blockIdx.x;
    const int tid = threadIdx.x;
    const int w = tid >> 5, lane = tid & 31;

    if (b == 0) {
        __shared__ int hist[NCLS];
        if (tid == 0) { g_ce = 0.0; g_done = 0u; }
        for (int c = tid; c < NCLS; c += 256) hist[c] = 0;
        __syncthreads();
        int nz = 0;
        for (int i = tid; i < BATCH / 2; i += 256)
            if (traw[2 * i + 1] != 0u) nz = 1;
        if (__syncthreads_or(nz)) {           // int32 layout
            for (int i = tid; i < BATCH; i += 256) {
                unsigned char c = (unsigned char)traw[i];
                g_tcls[i] = c;
                atomicAdd(&hist[c], 1);
            }
        } else {                              // little-endian int64 layout
            for (int i = tid; i < BATCH; i += 256) {
                unsigned char c = (unsigned char)traw[2 * i];
                g_tcls[i] = c;
                atomicAdd(&hist[c], 1);
            }
        }
        __syncthreads();
        for (int c = tid; c < NCLS; c += 256) g_chist[c] = hist[c];
        __threadfence();
        __syncthreads();
        if (tid == 0) atomicExch(&g_ready, 1u);
    } else if (b <= NORM_BLKS) {
        const int row = (b - 1) * 8 + w;
        const float4* xr = (const float4*)(x + (size_t)row * DD);
        float4 v[4];
        float s = 0.0f;
#pragma unroll
        for (int k = 0; k < 4; k++) {
            v[k] = xr[lane + 32 * k];
            s += v[k].x * v[k].x + v[k].y * v[k].y + v[k].z * v[k].z + v[k].w * v[k].w;
        }
#pragma unroll
        for (int o = 16; o > 0; o >>= 1) s += __shfl_xor_sync(0xffffffffu, s, o);
        const float inv = 127.0f / fmaxf(sqrtf(s), 1e-12f);
        char4* qr = (char4*)(g_q + (size_t)row * DD);
#pragma unroll
        for (int k = 0; k < 4; k++) {
            char4 q;
            q.x = (signed char)__float2int_rn(v[k].x * inv);
            q.y = (signed char)__float2int_rn(v[k].y * inv);
            q.z = (signed char)__float2int_rn(v[k].z * inv);
            q.w = (signed char)__float2int_rn(v[k].w * inv);
            qr[lane + 32 * k] = q;
        }
    } else if (b <= NORM_BLKS + CE_BLKS) {
        if (tid == 0) { while (atomicAdd(&g_ready, 0u) == 0u) {} }
        __syncthreads();
        const int i = (b - 1 - NORM_BLKS) * 8 + w;
        const float* p = pred + (size_t)i * NCLS;
        float m = -3.0e38f, slin = 0.0f;
#pragma unroll
        for (int k = 0; k < 7; k++) {
            int c = lane + 32 * k;
            if (c < NCLS) { float v = p[c]; m = fmaxf(m, v); slin += v; }
        }
#pragma unroll
        for (int o = 16; o > 0; o >>= 1) {
            m = fmaxf(m, __shfl_xor_sync(0xffffffffu, m, o));
            slin += __shfl_xor_sync(0xffffffffu, slin, o);
        }
        float se = 0.0f;
#pragma unroll
        for (int k = 0; k < 7; k++) {
            int c = lane + 32 * k;
            if (c < NCLS) se += __expf(p[c] - m);
        }
#pragma unroll
        for (int o = 16; o > 0; o >>= 1) se += __shfl_xor_sync(0xffffffffu, se, o);
        if (lane == 0) {
            float lse = m + __logf(se);
            int t = (int)g_tcls[i];
            float loss = 0.9f * (lse - p[t]) + 0.1f * (lse - slin / (float)NCLS);
            atomicAdd(&g_ce, (double)loss);
        }
    } else {
        const int z = b - 1 - NORM_BLKS - CE_BLKS;
        float4* dst = (float4*)(g_rows) + (size_t)z * (NR * 8 / 4 / ZBLK);
        for (int i = tid; i < NR * 8 / 4 / ZBLK; i += 256)
            dst[i] = make_float4(0.f, 0.f, 0.f, 0.f);
    }
}

// ---------------- fused symmetric int8 GEMM + masked reductions + final assemble ----------------
__device__ __forceinline__ void cp_async16(void* smem_dst, const void* gmem_src) {
    unsigned s = (unsigned)__cvta_generic_to_shared(smem_dst);
    asm volatile("cp.async.cg.shared.global [%0], [%1], 16;\n" :: "r"(s), "l"(gmem_src));
}

#define LDSB 80         // int8 row stride bytes: 64 + 16 pad (conflict-free LDSM)
#define LDG 132         // staging row stride (int32 elems)
#define STG_ELEMS (128 * LDSB)           // per-tensor per-stage bytes
#define STAGE_ELEMS (2 * STG_ELEMS)      // A+B per stage (20480 B)
#define GEMM_SMEM (128 * LDG * 4)        // staging 67584 B >= 3*STAGE_ELEMS=61440
#define INV_Q2 (1.0f / 16129.0f)         // 1/127^2
#define NTILES 2080

__global__ void __launch_bounds__(256) gemm_fused_kernel(float* out) {
    extern __shared__ char dsm[];
    signed char* sm = (signed char*)dsm;              // [3][A:128*80 | B:128*80]
    int* stgi = (int*)dsm;                            // 128*LDG int32 (reused)
    __shared__ unsigned char gA[32], gB[32];          // per-group (4 rows) class codes
    __shared__ int s_last;
    __shared__ double s_red[8];

    constexpr int NKIT = DD / 64;                     // 8 K-iterations

    // triangular tile decode: blockIdx.x in [0, 2080)
    int idx = blockIdx.x;
    int r = 0;
    while (idx >= 64 - r) { idx -= 64 - r; r++; }
    const int bm = r * 128;
    const int bn = (r + idx) * 128;

    const int tid = threadIdx.x;
    const int warp = tid >> 5;
    const int wm = (warp & 3) * 32;
    const int wn = (warp >> 2) * 64;

    auto load_stage = [&](int k0, int s) {
        signed char* As = sm + s * STAGE_ELEMS;
        signed char* Bs = As + STG_ELEMS;
#pragma unroll
        for (int it = 0; it < 2; it++) {
            int c = it * 256 + tid;                   // 512 chunks of 16B per tensor
            int row = c >> 2;
            int col = (c & 3) * 16;
            cp_async16(&As[row * LDSB + col], g_q + (size_t)(bm + row) * DD + k0 * 64 + col);
            cp_async16(&Bs[row * LDSB + col], g_q + (size_t)(bn + row) * DD + k0 * 64 + col);
        }
    };

    wmma::fragment<wmma::accumulator, 16, 16, 16, int> acc[2][4];
#pragma unroll
    for (int i = 0; i < 2; i++)
#pragma unroll
        for (int j = 0; j < 4; j++) wmma::fill_fragment(acc[i][j], 0);

    load_stage(0, 0);
    asm volatile("cp.async.commit_group;\n");
    load_stage(1, 1);
    asm volatile("cp.async.commit_group;\n");

    for (int k0 = 0; k0 < NKIT; k0++) {
        if (k0 < NKIT - 1) asm volatile("cp.async.wait_group 1;\n");
        else               asm volatile("cp.async.wait_group 0;\n");
        __syncthreads();
        if (k0 + 2 < NKIT) {
            load_stage(k0 + 2, (k0 + 2) % 3);
            asm volatile("cp.async.commit_group;\n");
        }
        const int s = k0 % 3;
        const signed char* As = sm + s * STAGE_ELEMS;
        const signed char* Bs = As + STG_ELEMS;
#pragma unroll
        for (int kk = 0; kk < 4; kk++) {
            wmma::fragment<wmma::matrix_a, 16, 16, 16, signed char, wmma::row_major> a[2];
            wmma::fragment<wmma::matrix_b, 16, 16, 16, signed char, wmma::col_major> bfr[4];
#pragma unroll
            for (int i = 0; i < 2; i++)
                wmma::load_matrix_sync(a[i], &As[(wm + i * 16) * LDSB + kk * 16], LDSB);
#pragma unroll
            for (int j = 0; j < 4; j++)
                wmma::load_matrix_sync(bfr[j], &Bs[(wn + j * 16) * LDSB + kk * 16], LDSB);
#pragma unroll
            for (int i = 0; i < 2; i++)
#pragma unroll
                for (int j = 0; j < 4; j++) wmma::mma_sync(acc[i][j], a[i], bfr[j], acc[i][j]);
        }
    }
    __syncthreads();

    // stage int32 tile in smem
#pragma unroll
    for (int i = 0; i < 2; i++)
#pragma unroll
        for (int j = 0; j < 4; j++)
            wmma::store_matrix_sync(stgi + (size_t)(wm + i * 16) * LDG + wn + j * 16,
                                    acc[i][j], LDG, wmma::mem_row_major);
    if (tid < 32) gA[tid] = g_tcls[(bm >> 2) + tid];
    else if (tid < 64) gB[tid - 32] = g_tcls[(bn >> 2) + (tid - 32)];
    __syncthreads();

    // ---- row pass: 2 threads per anchor row (bm+a) ----
    {
        const int a = tid >> 1, h = tid & 1;
        const int myc = gA[a >> 2], pi = a & 3;
        float T = 0.f, P = 0.f, Q = 0.f, R = 0.f, Pv = 0.f, Qv = 0.f, Rv = 0.f;
        const int4* rp = (const int4*)(stgi + (size_t)a * LDG + h * 64);
#pragma unroll
        for (int g = 0; g < 16; g++) {
            int4 q4 = rp[g];
            float v0 = (float)q4.x * INV_Q2, v1 = (float)q4.y * INV_Q2;
            float v2 = (float)q4.z * INV_Q2, v3 = (float)q4.w * INV_Q2;
            float e0 = __expf(v0), e1 = __expf(v1), e2 = __expf(v2), e3 = __expf(v3);
            float s = (e0 + e1) + (e2 + e3);
            float vs = (v0 + v1) + (v2 + v3);
            float ep = pi == 0 ? e0 : pi == 1 ? e1 : pi == 2 ? e2 : e3;
            float vp = pi == 0 ? v0 : pi == 1 ? v1 : pi == 2 ? v2 : v3;
            float m = (gB[h * 16 + g] == myc) ? 1.0f : 0.0f;
            T += s;
            P += m * ep;          Pv += m * vp;
            R += m * (s - ep);    Rv += m * (vs - vp);
            Q += (1.0f - m) * ep; Qv += (1.0f - m) * vp;
        }
        T += __shfl_xor_sync(0xffffffffu, T, 1);
        P += __shfl_xor_sync(0xffffffffu, P, 1);
        Q += __shfl_xor_sync(0xffffffffu, Q, 1);
        R += __shfl_xor_sync(0xffffffffu, R, 1);
        Pv += __shfl_xor_sync(0xffffffffu, Pv, 1);
        Qv += __shfl_xor_sync(0xffffffffu, Qv, 1);
        Rv += __shfl_xor_sync(0xffffffffu, Rv, 1);
        if (h == 0) {
            float* d = g_rows + (size_t)(bm + a) * 8;
            atomicAdd(d + 0, T);  atomicAdd(d + 1, P);  atomicAdd(d + 2, Q);
            atomicAdd(d + 3, R);  atomicAdd(d + 4, Pv); atomicAdd(d + 5, Qv);
            atomicAdd(d + 6, Rv);
        }
    }

    // ---- col pass (off-diagonal only) ----
    if (bm != bn) {
        const int c = tid >> 1, h = tid & 1;
        const int myc = gB[c >> 2], pi = c & 3;
        float T = 0.f, P = 0.f, Q = 0.f, R = 0.f, Pv = 0.f, Qv = 0.f, Rv = 0.f;
#pragma unroll
        for (int g = 0; g < 16; g++) {
            const int j0 = h * 64 + g * 4;
            float v0 = (float)stgi[(j0 + 0) * LDG + c] * INV_Q2;
            float v1 = (float)stgi[(j0 + 1) * LDG + c] * INV_Q2;
            float v2 = (float)stgi[(j0 + 2) * LDG + c] * INV_Q2;
            float v3 = (float)stgi[(j0 + 3) * LDG + c] * INV_Q2;
            float e0 = __expf(v0), e1 = __expf(v1), e2 = __expf(v2), e3 = __expf(v3);
            float s = (e0 + e1) + (e2 + e3);
            float vs = (v0 + v1) + (v2 + v3);
            float ep = pi == 0 ? e0 : pi == 1 ? e1 : pi == 2 ? e2 : e3;
            float vp = pi == 0 ? v0 : pi == 1 ? v1 : pi == 2 ? v2 : v3;
            float m = (gA[h * 16 + g] == myc) ? 1.0f : 0.0f;
            T += s;
            P += m * ep;          Pv += m * vp;
            R += m * (s - ep);    Rv += m * (vs - vp);
            Q += (1.0f - m) * ep; Qv += (1.0f - m) * vp;
        }
        T += __shfl_xor_sync(0xffffffffu, T, 1);
        P += __shfl_xor_sync(0xffffffffu, P, 1);
        Q += __shfl_xor_sync(0xffffffffu, Q, 1);
        R += __shfl_xor_sync(0xffffffffu, R, 1);
        Pv += __shfl_xor_sync(0xffffffffu, Pv, 1);
        Qv += __shfl_xor_sync(0xffffffffu, Qv, 1);
        Rv += __shfl_xor_sync(0xffffffffu, Rv, 1);
        if (h == 0) {
            float* d = g_rows + (size_t)(bn + c) * 8;
            atomicAdd(d + 0, T);  atomicAdd(d + 1, P);  atomicAdd(d + 2, Q);
            atomicAdd(d + 3, R);  atomicAdd(d + 4, Pv); atomicAdd(d + 5, Qv);
            atomicAdd(d + 6, Rv);
        }
    }

    // ---- last-block assemble: E1=T-P, E2=E1-Q-R; x=e^{-v}E >= ~700:
    // sum_pos log1p = n*logE - sum(v) + sum(e^v)/E
    __threadfence();
    __syncthreads();
    if (tid == 0) {
        unsigned done = atomicAdd(&g_done, 1u);
        s_last = (done == NTILES - 1u) ? 1 : 0;
    }
    __syncthreads();
    if (s_last) {
        __threadfence();
        double accd = 0.0;
        for (int i = tid; i < NR; i += 256) {
            float4 b0 = __ldcg((const float4*)(g_rows + (size_t)i * 8));
            float4 b1 = __ldcg((const float4*)(g_rows + (size_t)i * 8 + 4));
            float T = b0.x, P = b0.y, Q = b0.z, R = b0.w;
            float Pv = b1.x, Qv = b1.y, Rv = b1.z;
            float E1 = T - P;
            float E2 = E1 - Q - R;
            float ct = (float)g_chist[g_tcls[i >> 2]];
            float c = ct * __logf(E1) - Pv + P / E1
                    + (2048.0f + 2.0f * ct) * __logf(E2) - (Qv + Rv) + (Q + R) / E2;
            accd += (double)c;
        }
#pragma unroll
        for (int o = 16; o > 0; o >>= 1) accd += __shfl_xor_sync(0xffffffffu, accd, o);
        if ((tid & 31) == 0) s_red[tid >> 5] = accd;
        __syncthreads();
        if (warp == 0) {
            accd = (tid < 8) ? s_red[tid] : 0.0;
#pragma unroll
            for (int o = 4; o > 0; o >>= 1) accd += __shfl_xor_sync(0xffffffffu, accd, o);
            if (tid == 0) {
                out[0] = (float)(g_ce / (double)BATCH + 0.5 * (accd / (double)NR));
                g_done = 0u;
                g_ready = 0u;
            }
        }
    }
}

// ---------------- launch ----------------
extern "C" void kernel_launch(void* const* d_in, const int* in_sizes, int n_in,
                              void* d_out, int out_size) {
    const float* pred = nullptr;
    const float* x_part = nullptr;
    const unsigned int* traw = nullptr;
    for (int i = 0; i < n_in; i++) {
        if (in_sizes[i] == BATCH * NCLS)      pred   = (const float*)d_in[i];
        else if (in_sizes[i] == NR * DD)      x_part = (const float*)d_in[i];
        else if (in_sizes[i] == BATCH)        traw   = (const unsigned int*)d_in[i];
    }
    float* out = (float*)d_out;

    cudaFuncSetAttribute(gemm_fused_kernel, cudaFuncAttributeMaxDynamicSharedMemorySize,
                         GEMM_SMEM);

    norm_ce_kernel<<<NC_GRID, 256>>>(x_part, pred, traw);
    gemm_fused_kernel<<<NTILES, 256, GEMM_SMEM>>>(out);
}

// round 15
// speedup vs baseline: 1.0939x; 1.0939x over previous
#include <cuda_runtime.h>
#include <cuda_bf16.h>
#include <mma.h>
#include <cstdint>
#include <math.h>

using namespace nvcuda;

#define NR 8192
#define DD 512
#define BATCH 2048
#define NCLS 200

// ---------------- scratch (__device__ globals, no allocation) ----------------
__device__ signed char g_q[(size_t)NR * DD];     // quantized normalized features (4 MB)
__device__ float g_rows[(size_t)NR * 8];         // per-row {T,P,Q,R,Pv,Qv,Rv,pad} (256 KB)
__device__ int g_chist[NCLS];
__device__ double g_ce;
__device__ double g_np;
__device__ unsigned g_done;
__device__ unsigned g_ready;
__device__ unsigned char g_tcls[BATCH];

// ---------------- fused decode + normalize(+quantize) + CE + zeroing ----------------
#define NORM_BLKS (NR / 8)          // 1024
#define CE_BLKS (BATCH / 8)         // 256
#define ZBLK 16
#define NC_GRID (1 + NORM_BLKS + CE_BLKS + ZBLK)

__global__ void __launch_bounds__(256) norm_ce_kernel(const float* __restrict__ x,
                                                      const float* __restrict__ pred,
                                                      const unsigned int* __restrict__ traw) {
    const int b = blockIdx.x;
    const int tid = threadIdx.x;
    const int w = tid >> 5, lane = tid & 31;

    if (b == 0) {
        __shared__ int hist[NCLS];
        if (tid == 0) { g_ce = 0.0; g_np = 0.0; g_done = 0u; }
        for (int c = tid; c < NCLS; c += 256) hist[c] = 0;
        __syncthreads();
        int nz = 0;
        for (int i = tid; i < BATCH / 2; i += 256)
            if (traw[2 * i + 1] != 0u) nz = 1;
        if (__syncthreads_or(nz)) {           // int32 layout
            for (int i = tid; i < BATCH; i += 256) {
                unsigned char c = (unsigned char)traw[i];
                g_tcls[i] = c;
                atomicAdd(&hist[c], 1);
            }
        } else {                              // little-endian int64 layout
            for (int i = tid; i < BATCH; i += 256) {
                unsigned char c = (unsigned char)traw[2 * i];
                g_tcls[i] = c;
                atomicAdd(&hist[c], 1);
            }
        }
        __syncthreads();
        for (int c = tid; c < NCLS; c += 256) g_chist[c] = hist[c];
        __threadfence();
        __syncthreads();
        if (tid == 0) atomicExch(&g_ready, 1u);
    } else if (b <= NORM_BLKS) {
        const int row = (b - 1) * 8 + w;
        const float4* xr = (const float4*)(x + (size_t)row * DD);
        float4 v[4];
        float s = 0.0f;
#pragma unroll
        for (int k = 0; k < 4; k++) {
            v[k] = xr[lane + 32 * k];
            s += v[k].x * v[k].x + v[k].y * v[k].y + v[k].z * v[k].z + v[k].w * v[k].w;
        }
#pragma unroll
        for (int o = 16; o > 0; o >>= 1) s += __shfl_xor_sync(0xffffffffu, s, o);
        const float inv = 127.0f / fmaxf(sqrtf(s), 1e-12f);
        char4* qr = (char4*)(g_q + (size_t)row * DD);
#pragma unroll
        for (int k = 0; k < 4; k++) {
            char4 q;
            q.x = (signed char)__float2int_rn(v[k].x * inv);
            q.y = (signed char)__float2int_rn(v[k].y * inv);
            q.z = (signed char)__float2int_rn(v[k].z * inv);
            q.w = (signed char)__float2int_rn(v[k].w * inv);
            qr[lane + 32 * k] = q;
        }
    } else if (b <= NORM_BLKS + CE_BLKS) {
        if (tid == 0) { while (atomicAdd(&g_ready, 0u) == 0u) {} }
        __syncthreads();
        const int i = (b - 1 - NORM_BLKS) * 8 + w;
        const float* p = pred + (size_t)i * NCLS;
        float m = -3.0e38f, slin = 0.0f;
#pragma unroll
        for (int k = 0; k < 7; k++) {
            int c = lane + 32 * k;
            if (c < NCLS) { float v = p[c]; m = fmaxf(m, v); slin += v; }
        }
#pragma unroll
        for (int o = 16; o > 0; o >>= 1) {
            m = fmaxf(m, __shfl_xor_sync(0xffffffffu, m, o));
            slin += __shfl_xor_sync(0xffffffffu, slin, o);
        }
        float se = 0.0f;
#pragma unroll
        for (int k = 0; k < 7; k++) {
            int c = lane + 32 * k;
            if (c < NCLS) se += __expf(p[c] - m);
        }
#pragma unroll
        for (int o = 16; o > 0; o >>= 1) se += __shfl_xor_sync(0xffffffffu, se, o);
        if (lane == 0) {
            float lse = m + __logf(se);
            int t = (int)g_tcls[i];
            float loss = 0.9f * (lse - p[t]) + 0.1f * (lse - slin / (float)NCLS);
            atomicAdd(&g_ce, (double)loss);
        }
    } else {
        const int z = b - 1 - NORM_BLKS - CE_BLKS;
        float4* dst = (float4*)(g_rows) + (size_t)z * (NR * 8 / 4 / ZBLK);
        for (int i = tid; i < NR * 8 / 4 / ZBLK; i += 256)
            dst[i] = make_float4(0.f, 0.f, 0.f, 0.f);
    }
}

// ---------------- fused symmetric int8 GEMM + masked reductions ----------------
__device__ __forceinline__ void cp_async16(void* smem_dst, const void* gmem_src) {
    unsigned s = (unsigned)__cvta_generic_to_shared(smem_dst);
    asm volatile("cp.async.cg.shared.global [%0], [%1], 16;\n" :: "r"(s), "l"(gmem_src));
}

#define LDSB 80         // int8 row stride bytes: 64 + 16 pad (conflict-free LDSM)
#define LDG 132         // staging row stride (int32 elems)
#define STG_ELEMS (128 * LDSB)           // per-tensor per-stage bytes
#define STAGE_ELEMS (2 * STG_ELEMS)      // A+B per stage (20480 B)
#define NSTAGE 4
#define GEMM_SMEM (NSTAGE * STAGE_ELEMS) // 81920 B >= staging 67584 B
#define INV_Q2 (1.0f / 16129.0f)         // 1/127^2
#define NTILES 2080

__global__ void __launch_bounds__(256, 2) gemm_fused_kernel() {
    extern __shared__ char dsm[];
    signed char* sm = (signed char*)dsm;              // [4][A:128*80 | B:128*80]
    int* stgi = (int*)dsm;                            // 128*LDG int32 (reused)
    __shared__ unsigned char gA[32], gB[32];          // per-group (4 rows) class codes

    constexpr int NKIT = DD / 64;                     // 8 K-iterations

    // triangular tile decode: blockIdx.x in [0, 2080)
    int idx = blockIdx.x;
    int r = 0;
    while (idx >= 64 - r) { idx -= 64 - r; r++; }
    const int bm = r * 128;
    const int bn = (r + idx) * 128;

    const int tid = threadIdx.x;
    const int warp = tid >> 5;
    const int wm = (warp & 3) * 32;
    const int wn = (warp >> 2) * 64;

    auto load_stage = [&](int k0, int s) {
        signed char* As = sm + s * STAGE_ELEMS;
        signed char* Bs = As + STG_ELEMS;
#pragma unroll
        for (int it = 0; it < 2; it++) {
            int c = it * 256 + tid;                   // 512 chunks of 16B per tensor
            int row = c >> 2;
            int col = (c & 3) * 16;
            cp_async16(&As[row * LDSB + col], g_q + (size_t)(bm + row) * DD + k0 * 64 + col);
            cp_async16(&Bs[row * LDSB + col], g_q + (size_t)(bn + row) * DD + k0 * 64 + col);
        }
    };

    wmma::fragment<wmma::accumulator, 16, 16, 16, int> acc[2][4];
#pragma unroll
    for (int i = 0; i < 2; i++)
#pragma unroll
        for (int j = 0; j < 4; j++) wmma::fill_fragment(acc[i][j], 0);

    load_stage(0, 0);
    asm volatile("cp.async.commit_group;\n");
    load_stage(1, 1);
    asm volatile("cp.async.commit_group;\n");
    load_stage(2, 2);
    asm volatile("cp.async.commit_group;\n");

    for (int k0 = 0; k0 < NKIT; k0++) {
        asm volatile("cp.async.wait_group 2;\n");      // stage k0 landed
        __syncthreads();                               // all warps done reading (k0-1)%4
        if (k0 + 3 < NKIT) load_stage(k0 + 3, (k0 + 3) & 3);
        asm volatile("cp.async.commit_group;\n");      // always commit (count alignment)

        const int s = k0 & 3;
        const signed char* As = sm + s * STAGE_ELEMS;
        const signed char* Bs = As + STG_ELEMS;

        // fragment double-buffer across kk: load kk+1 while MMA kk
        wmma::fragment<wmma::matrix_a, 16, 16, 16, signed char, wmma::row_major> fa[2][2];
        wmma::fragment<wmma::matrix_b, 16, 16, 16, signed char, wmma::col_major> fb[2][4];
#pragma unroll
        for (int i = 0; i < 2; i++)
            wmma::load_matrix_sync(fa[0][i], &As[(wm + i * 16) * LDSB], LDSB);
#pragma unroll
        for (int j = 0; j < 4; j++)
            wmma::load_matrix_sync(fb[0][j], &Bs[(wn + j * 16) * LDSB], LDSB);
#pragma unroll
        for (int kk = 0; kk < 4; kk++) {
            const int cur = kk & 1, nxt = cur ^ 1;
            if (kk < 3) {
#pragma unroll
                for (int i = 0; i < 2; i++)
                    wmma::load_matrix_sync(fa[nxt][i],
                                           &As[(wm + i * 16) * LDSB + (kk + 1) * 16], LDSB);
#pragma unroll
                for (int j = 0; j < 4; j++)
                    wmma::load_matrix_sync(fb[nxt][j],
                                           &Bs[(wn + j * 16) * LDSB + (kk + 1) * 16], LDSB);
            }
#pragma unroll
            for (int i = 0; i < 2; i++)
#pragma unroll
                for (int j = 0; j < 4; j++)
                    wmma::mma_sync(acc[i][j], fa[cur][i], fb[cur][j], acc[i][j]);
        }
    }
    __syncthreads();                                   // before reusing smem as staging

    // stage int32 tile in smem
#pragma unroll
    for (int i = 0; i < 2; i++)
#pragma unroll
        for (int j = 0; j < 4; j++)
            wmma::store_matrix_sync(stgi + (size_t)(wm + i * 16) * LDG + wn + j * 16,
                                    acc[i][j], LDG, wmma::mem_row_major);
    if (tid < 32) gA[tid] = g_tcls[(bm >> 2) + tid];
    else if (tid < 64) gB[tid - 32] = g_tcls[(bn >> 2) + (tid - 32)];
    __syncthreads();

    // ---- row pass: 2 threads per anchor row (bm+a) ----
    {
        const int a = tid >> 1, h = tid & 1;
        const int myc = gA[a >> 2], pi = a & 3;
        float T = 0.f, P = 0.f, Q = 0.f, R = 0.f, Pv = 0.f, Qv = 0.f, Rv = 0.f;
        const int4* rp = (const int4*)(stgi + (size_t)a * LDG + h * 64);
#pragma unroll
        for (int g = 0; g < 16; g++) {
            int4 q4 = rp[g];
            float v0 = (float)q4.x * INV_Q2, v1 = (float)q4.y * INV_Q2;
            float v2 = (float)q4.z * INV_Q2, v3 = (float)q4.w * INV_Q2;
            float e0 = __expf(v0), e1 = __expf(v1), e2 = __expf(v2), e3 = __expf(v3);
            float s = (e0 + e1) + (e2 + e3);
            float vs = (v0 + v1) + (v2 + v3);
            float ep = pi == 0 ? e0 : pi == 1 ? e1 : pi == 2 ? e2 : e3;
            float vp = pi == 0 ? v0 : pi == 1 ? v1 : pi == 2 ? v2 : v3;
            float m = (gB[h * 16 + g] == myc) ? 1.0f : 0.0f;
            T += s;
            P += m * ep;          Pv += m * vp;
            R += m * (s - ep);    Rv += m * (vs - vp);
            Q += (1.0f - m) * ep; Qv += (1.0f - m) * vp;
        }
        T += __shfl_xor_sync(0xffffffffu, T, 1);
        P += __shfl_xor_sync(0xffffffffu, P, 1);
        Q += __shfl_xor_sync(0xffffffffu, Q, 1);
        R += __shfl_xor_sync(0xffffffffu, R, 1);
        Pv += __shfl_xor_sync(0xffffffffu, Pv, 1);
        Qv += __shfl_xor_sync(0xffffffffu, Qv, 1);
        Rv += __shfl_xor_sync(0xffffffffu, Rv, 1);
        if (h == 0) {
            float* d = g_rows + (size_t)(bm + a) * 8;
            atomicAdd(d + 0, T);  atomicAdd(d + 1, P);  atomicAdd(d + 2, Q);
            atomicAdd(d + 3, R);  atomicAdd(d + 4, Pv); atomicAdd(d + 5, Qv);
            atomicAdd(d + 6, Rv);
        }
    }

    // ---- col pass (off-diagonal only) ----
    if (bm != bn) {
        const int c = tid >> 1, h = tid & 1;
        const int myc = gB[c >> 2], pi = c & 3;
        float T = 0.f, P = 0.f, Q = 0.f, R = 0.f, Pv = 0.f, Qv = 0.f, Rv = 0.f;
#pragma unroll
        for (int g = 0; g < 16; g++) {
            const int j0 = h * 64 + g * 4;
            float v0 = (float)stgi[(j0 + 0) * LDG + c] * INV_Q2;
            float v1 = (float)stgi[(j0 + 1) * LDG + c] * INV_Q2;
            float v2 = (float)stgi[(j0 + 2) * LDG + c] * INV_Q2;
            float v3 = (float)stgi[(j0 + 3) * LDG + c] * INV_Q2;
            float e0 = __expf(v0), e1 = __expf(v1), e2 = __expf(v2), e3 = __expf(v3);
            float s = (e0 + e1) + (e2 + e3);
            float vs = (v0 + v1) + (v2 + v3);
            float ep = pi == 0 ? e0 : pi == 1 ? e1 : pi == 2 ? e2 : e3;
            float vp = pi == 0 ? v0 : pi == 1 ? v1 : pi == 2 ? v2 : v3;
            float m = (gA[h * 16 + g] == myc) ? 1.0f : 0.0f;
            T += s;
            P += m * ep;          Pv += m * vp;
            R += m * (s - ep);    Rv += m * (vs - vp);
            Q += (1.0f - m) * ep; Qv += (1.0f - m) * vp;
        }
        T += __shfl_xor_sync(0xffffffffu, T, 1);
        P += __shfl_xor_sync(0xffffffffu, P, 1);
        Q += __shfl_xor_sync(0xffffffffu, Q, 1);
        R += __shfl_xor_sync(0xffffffffu, R, 1);
        Pv += __shfl_xor_sync(0xffffffffu, Pv, 1);
        Qv += __shfl_xor_sync(0xffffffffu, Qv, 1);
        Rv += __shfl_xor_sync(0xffffffffu, Rv, 1);
        if (h == 0) {
            float* d = g_rows + (size_t)(bn + c) * 8;
            atomicAdd(d + 0, T);  atomicAdd(d + 1, P);  atomicAdd(d + 2, Q);
            atomicAdd(d + 3, R);  atomicAdd(d + 4, Pv); atomicAdd(d + 5, Qv);
            atomicAdd(d + 6, Rv);
        }
    }
}

// ---------------- assemble (32 blocks) + last-block finalize ----------------
// E1 = T-P; E2 = T-P-Q-R.  x = e^{-v}E >= ~700:
// sum_pos log1p(e^{-v}E) = n*logE - sum(v) + sum(e^v)/E
__global__ void assemble_kernel(float* out) {
    const int i = blockIdx.x * 256 + threadIdx.x;      // 8192 threads over 32 blocks
    const float* b = g_rows + (size_t)i * 8;
    float T = b[0], P = b[1], Q = b[2], R = b[3], Pv = b[4], Qv = b[5], Rv = b[6];
    float E1 = T - P;
    float E2 = E1 - Q - R;
    float ct = (float)g_chist[g_tcls[i >> 2]];
    float c = ct * __logf(E1) - Pv + P / E1
            + (2048.0f + 2.0f * ct) * __logf(E2) - (Qv + Rv) + (Q + R) / E2;
    double d = (double)c;
#pragma unroll
    for (int o = 16; o > 0; o >>= 1) d += __shfl_xor_sync(0xffffffffu, d, o);
    if ((threadIdx.x & 31) == 0) atomicAdd(&g_np, d);
    __syncthreads();
    if (threadIdx.x == 0) {
        __threadfence();
        unsigned done = atomicAdd(&g_done, 1u);
        if (done == 31u) {                             // last block finalizes
            __threadfence();
            double np = atomicAdd(&g_np, 0.0);         // ordered read
            double ce = g_ce;
            out[0] = (float)(ce / (double)BATCH + 0.5 * (np / (double)NR));
            g_done = 0u;
            g_ready = 0u;                              // reset for next replay
        }
    }
}

// ---------------- launch ----------------
extern "C" void kernel_launch(void* const* d_in, const int* in_sizes, int n_in,
                              void* d_out, int out_size) {
    const float* pred = nullptr;
    const float* x_part = nullptr;
    const unsigned int* traw = nullptr;
    for (int i = 0; i < n_in; i++) {
        if (in_sizes[i] == BATCH * NCLS)      pred   = (const float*)d_in[i];
        else if (in_sizes[i] == NR * DD)      x_part = (const float*)d_in[i];
        else if (in_sizes[i] == BATCH)        traw   = (const unsigned int*)d_in[i];
    }
    float* out = (float*)d_out;

    cudaFuncSetAttribute(gemm_fused_kernel, cudaFuncAttributeMaxDynamicSharedMemorySize,
                         GEMM_SMEM);

    norm_ce_kernel<<<NC_GRID, 256>>>(x_part, pred, traw);
    gemm_fused_kernel<<<NTILES, 256, GEMM_SMEM>>>();
    assemble_kernel<<<32, 256>>>(out);
}

// round 16
// speedup vs baseline: 1.1367x; 1.0391x over previous
#include <cuda_runtime.h>
#include <cuda_bf16.h>
#include <mma.h>
#include <cstdint>
#include <math.h>

using namespace nvcuda;

#define NR 8192
#define DD 512
#define BATCH 2048
#define NCLS 200

// ---------------- scratch (__device__ globals, no allocation) ----------------
__device__ signed char g_q[(size_t)NR * DD];     // quantized normalized features (4 MB)
__device__ float g_rows[(size_t)NR * 8];         // per-row {T,P,Q,R,Pv,Qv,Rv,pad} (256 KB)
__device__ int g_chist[NCLS];
__device__ double g_ce;
__device__ double g_np;
__device__ unsigned g_done;
__device__ unsigned g_ready;
__device__ unsigned char g_tcls[BATCH];

// ---------------- fused decode + normalize(+quantize) + CE + zeroing ----------------
// block 0: decode targets + histogram; blocks 1..512: 16 rows each (2 rows/warp);
// next 128: 16 CE samples each (2/warp, spin on ready); last 16: zero g_rows.
#define NORM_BLKS (NR / 16)         // 512
#define CE_BLKS (BATCH / 16)        // 128
#define ZBLK 16
#define NC_GRID (1 + NORM_BLKS + CE_BLKS + ZBLK)

__global__ void __launch_bounds__(256) norm_ce_kernel(const float* __restrict__ x,
                                                      const float* __restrict__ pred,
                                                      const unsigned int* __restrict__ traw) {
    const int b = blockIdx.x;
    const int tid = threadIdx.x;
    const int w = tid >> 5, lane = tid & 31;

    if (b == 0) {
        __shared__ int hist[NCLS];
        if (tid == 0) { g_ce = 0.0; g_np = 0.0; g_done = 0u; }
        for (int c = tid; c < NCLS; c += 256) hist[c] = 0;
        __syncthreads();
        int nz = 0;
        for (int i = tid; i < BATCH / 2; i += 256)
            if (traw[2 * i + 1] != 0u) nz = 1;
        if (__syncthreads_or(nz)) {           // int32 layout
            for (int i = tid; i < BATCH; i += 256) {
                unsigned char c = (unsigned char)traw[i];
                g_tcls[i] = c;
                atomicAdd(&hist[c], 1);
            }
        } else {                              // little-endian int64 layout
            for (int i = tid; i < BATCH; i += 256) {
                unsigned char c = (unsigned char)traw[2 * i];
                g_tcls[i] = c;
                atomicAdd(&hist[c], 1);
            }
        }
        __syncthreads();
        for (int c = tid; c < NCLS; c += 256) g_chist[c] = hist[c];
        __threadfence();
        __syncthreads();
        if (tid == 0) atomicExch(&g_ready, 1u);
    } else if (b <= NORM_BLKS) {
        // 2 rows per warp: 8 independent float4 loads in flight
        const int row0 = (b - 1) * 16 + w * 2;
        const float4* xr0 = (const float4*)(x + (size_t)row0 * DD);
        const float4* xr1 = (const float4*)(x + (size_t)(row0 + 1) * DD);
        float4 v0[4], v1[4];
        float s0 = 0.0f, s1 = 0.0f;
#pragma unroll
        for (int k = 0; k < 4; k++) v0[k] = xr0[lane + 32 * k];
#pragma unroll
        for (int k = 0; k < 4; k++) v1[k] = xr1[lane + 32 * k];
#pragma unroll
        for (int k = 0; k < 4; k++) {
            s0 += v0[k].x * v0[k].x + v0[k].y * v0[k].y + v0[k].z * v0[k].z + v0[k].w * v0[k].w;
            s1 += v1[k].x * v1[k].x + v1[k].y * v1[k].y + v1[k].z * v1[k].z + v1[k].w * v1[k].w;
        }
#pragma unroll
        for (int o = 16; o > 0; o >>= 1) {
            s0 += __shfl_xor_sync(0xffffffffu, s0, o);
            s1 += __shfl_xor_sync(0xffffffffu, s1, o);
        }
        const float inv0 = 127.0f / fmaxf(sqrtf(s0), 1e-12f);
        const float inv1 = 127.0f / fmaxf(sqrtf(s1), 1e-12f);
        char4* qr0 = (char4*)(g_q + (size_t)row0 * DD);
        char4* qr1 = (char4*)(g_q + (size_t)(row0 + 1) * DD);
#pragma unroll
        for (int k = 0; k < 4; k++) {
            char4 q;
            q.x = (signed char)__float2int_rn(v0[k].x * inv0);
            q.y = (signed char)__float2int_rn(v0[k].y * inv0);
            q.z = (signed char)__float2int_rn(v0[k].z * inv0);
            q.w = (signed char)__float2int_rn(v0[k].w * inv0);
            qr0[lane + 32 * k] = q;
        }
#pragma unroll
        for (int k = 0; k < 4; k++) {
            char4 q;
            q.x = (signed char)__float2int_rn(v1[k].x * inv1);
            q.y = (signed char)__float2int_rn(v1[k].y * inv1);
            q.z = (signed char)__float2int_rn(v1[k].z * inv1);
            q.w = (signed char)__float2int_rn(v1[k].w * inv1);
            qr1[lane + 32 * k] = q;
        }
    } else if (b <= NORM_BLKS + CE_BLKS) {
        if (tid == 0) { while (atomicAdd(&g_ready, 0u) == 0u) {} }
        __syncthreads();
        // 2 samples per warp
        const int i0 = (b - 1 - NORM_BLKS) * 16 + w * 2;
        const float* p0 = pred + (size_t)i0 * NCLS;
        const float* p1 = pred + (size_t)(i0 + 1) * NCLS;
        float pv0[7], pv1[7];
#pragma unroll
        for (int k = 0; k < 7; k++) {
            int c = lane + 32 * k;
            pv0[k] = (c < NCLS) ? p0[c] : -3.0e38f;
            pv1[k] = (c < NCLS) ? p1[c] : -3.0e38f;
        }
        float m0 = -3.0e38f, m1 = -3.0e38f, sl0 = 0.0f, sl1 = 0.0f;
#pragma unroll
        for (int k = 0; k < 7; k++) {
            m0 = fmaxf(m0, pv0[k]);
            m1 = fmaxf(m1, pv1[k]);
            if (lane + 32 * k < NCLS) { sl0 += pv0[k]; sl1 += pv1[k]; }
        }
#pragma unroll
        for (int o = 16; o > 0; o >>= 1) {
            m0 = fmaxf(m0, __shfl_xor_sync(0xffffffffu, m0, o));
            m1 = fmaxf(m1, __shfl_xor_sync(0xffffffffu, m1, o));
            sl0 += __shfl_xor_sync(0xffffffffu, sl0, o);
            sl1 += __shfl_xor_sync(0xffffffffu, sl1, o);
        }
        float se0 = 0.0f, se1 = 0.0f;
#pragma unroll
        for (int k = 0; k < 7; k++) {
            if (lane + 32 * k < NCLS) {
                se0 += __expf(pv0[k] - m0);
                se1 += __expf(pv1[k] - m1);
            }
        }
#pragma unroll
        for (int o = 16; o > 0; o >>= 1) {
            se0 += __shfl_xor_sync(0xffffffffu, se0, o);
            se1 += __shfl_xor_sync(0xffffffffu, se1, o);
        }
        if (lane == 0) {
            float lse0 = m0 + __logf(se0);
            float lse1 = m1 + __logf(se1);
            int t0 = (int)g_tcls[i0], t1 = (int)g_tcls[i0 + 1];
            float loss = 0.9f * (lse0 - p0[t0]) + 0.1f * (lse0 - sl0 / (float)NCLS)
                       + 0.9f * (lse1 - p1[t1]) + 0.1f * (lse1 - sl1 / (float)NCLS);
            atomicAdd(&g_ce, (double)loss);
        }
    } else {
        const int z = b - 1 - NORM_BLKS - CE_BLKS;
        float4* dst = (float4*)(g_rows) + (size_t)z * (NR * 8 / 4 / ZBLK);
        for (int i = tid; i < NR * 8 / 4 / ZBLK; i += 256)
            dst[i] = make_float4(0.f, 0.f, 0.f, 0.f);
    }
}

// ---------------- fused symmetric int8 GEMM + masked reductions ----------------
__device__ __forceinline__ void cp_async16(void* smem_dst, const void* gmem_src) {
    unsigned s = (unsigned)__cvta_generic_to_shared(smem_dst);
    asm volatile("cp.async.cg.shared.global [%0], [%1], 16;\n" :: "r"(s), "l"(gmem_src));
}

#define LDSB 80         // int8 row stride bytes: 64 + 16 pad (conflict-free LDSM)
#define LDG 132         // staging row stride (int32 elems)
#define STG_ELEMS (128 * LDSB)           // per-tensor per-stage bytes
#define STAGE_ELEMS (2 * STG_ELEMS)      // A+B per stage (20480 B)
#define NSTAGE 4
#define GEMM_SMEM (NSTAGE * STAGE_ELEMS) // 81920 B >= staging 67584 B
#define INV_Q2 (1.0f / 16129.0f)         // 1/127^2
#define NTILES 2080

__global__ void __launch_bounds__(256, 2) gemm_fused_kernel() {
    extern __shared__ char dsm[];
    signed char* sm = (signed char*)dsm;              // [4][A:128*80 | B:128*80]
    int* stgi = (int*)dsm;                            // 128*LDG int32 (reused)
    __shared__ unsigned char gA[32], gB[32];          // per-group (4 rows) class codes

    constexpr int NKIT = DD / 64;                     // 8 K-iterations

    // triangular tile decode: blockIdx.x in [0, 2080)
    int idx = blockIdx.x;
    int r = 0;
    while (idx >= 64 - r) { idx -= 64 - r; r++; }
    const int bm = r * 128;
    const int bn = (r + idx) * 128;

    const int tid = threadIdx.x;
    const int warp = tid >> 5;
    const int wm = (warp & 3) * 32;
    const int wn = (warp >> 2) * 64;

    // prefetch class bytes early (consumed after the K loop)
    if (tid < 32) gA[tid] = g_tcls[(bm >> 2) + tid];
    else if (tid < 64) gB[tid - 32] = g_tcls[(bn >> 2) + (tid - 32)];

    auto load_stage = [&](int k0, int s) {
        signed char* As = sm + s * STAGE_ELEMS;
        signed char* Bs = As + STG_ELEMS;
#pragma unroll
        for (int it = 0; it < 2; it++) {
            int c = it * 256 + tid;                   // 512 chunks of 16B per tensor
            int row = c >> 2;
            int col = (c & 3) * 16;
            cp_async16(&As[row * LDSB + col], g_q + (size_t)(bm + row) * DD + k0 * 64 + col);
            cp_async16(&Bs[row * LDSB + col], g_q + (size_t)(bn + row) * DD + k0 * 64 + col);
        }
    };

    wmma::fragment<wmma::accumulator, 16, 16, 16, int> acc[2][4];
#pragma unroll
    for (int i = 0; i < 2; i++)
#pragma unroll
        for (int j = 0; j < 4; j++) wmma::fill_fragment(acc[i][j], 0);

    load_stage(0, 0);
    asm volatile("cp.async.commit_group;\n");
    load_stage(1, 1);
    asm volatile("cp.async.commit_group;\n");
    load_stage(2, 2);
    asm volatile("cp.async.commit_group;\n");

    for (int k0 = 0; k0 < NKIT; k0++) {
        asm volatile("cp.async.wait_group 2;\n");      // stage k0 landed
        __syncthreads();                               // all warps done reading (k0-1)%4
        if (k0 + 3 < NKIT) load_stage(k0 + 3, (k0 + 3) & 3);
        asm volatile("cp.async.commit_group;\n");      // always commit (count alignment)

        const int s = k0 & 3;
        const signed char* As = sm + s * STAGE_ELEMS;
        const signed char* Bs = As + STG_ELEMS;

        // fragment double-buffer across kk: load kk+1 while MMA kk
        wmma::fragment<wmma::matrix_a, 16, 16, 16, signed char, wmma::row_major> fa[2][2];
        wmma::fragment<wmma::matrix_b, 16, 16, 16, signed char, wmma::col_major> fb[2][4];
#pragma unroll
        for (int i = 0; i < 2; i++)
            wmma::load_matrix_sync(fa[0][i], &As[(wm + i * 16) * LDSB], LDSB);
#pragma unroll
        for (int j = 0; j < 4; j++)
            wmma::load_matrix_sync(fb[0][j], &Bs[(wn + j * 16) * LDSB], LDSB);
#pragma unroll
        for (int kk = 0; kk < 4; kk++) {
            const int cur = kk & 1, nxt = cur ^ 1;
            if (kk < 3) {
#pragma unroll
                for (int i = 0; i < 2; i++)
                    wmma::load_matrix_sync(fa[nxt][i],
                                           &As[(wm + i * 16) * LDSB + (kk + 1) * 16], LDSB);
#pragma unroll
                for (int j = 0; j < 4; j++)
                    wmma::load_matrix_sync(fb[nxt][j],
                                           &Bs[(wn + j * 16) * LDSB + (kk + 1) * 16], LDSB);
            }
#pragma unroll
            for (int i = 0; i < 2; i++)
#pragma unroll
                for (int j = 0; j < 4; j++)
                    wmma::mma_sync(acc[i][j], fa[cur][i], fb[cur][j], acc[i][j]);
        }
    }
    __syncthreads();                                   // before reusing smem as staging

    // stage int32 tile in smem
#pragma unroll
    for (int i = 0; i < 2; i++)
#pragma unroll
        for (int j = 0; j < 4; j++)
            wmma::store_matrix_sync(stgi + (size_t)(wm + i * 16) * LDG + wn + j * 16,
                                    acc[i][j], LDG, wmma::mem_row_major);
    __syncthreads();

    // ---- row pass: 2 threads per anchor row (bm+a) ----
    {
        const int a = tid >> 1, h = tid & 1;
        const int myc = gA[a >> 2], pi = a & 3;
        float T = 0.f, P = 0.f, Q = 0.f, R = 0.f, Pv = 0.f, Qv = 0.f, Rv = 0.f;
        const int4* rp = (const int4*)(stgi + (size_t)a * LDG + h * 64);
#pragma unroll
        for (int g = 0; g < 16; g++) {
            int4 q4 = rp[g];
            float v0 = (float)q4.x * INV_Q2, v1 = (float)q4.y * INV_Q2;
            float v2 = (float)q4.z * INV_Q2, v3 = (float)q4.w * INV_Q2;
            float e0 = __expf(v0), e1 = __expf(v1), e2 = __expf(v2), e3 = __expf(v3);
            float s = (e0 + e1) + (e2 + e3);
            float vs = (v0 + v1) + (v2 + v3);
            float ep = pi == 0 ? e0 : pi == 1 ? e1 : pi == 2 ? e2 : e3;
            float vp = pi == 0 ? v0 : pi == 1 ? v1 : pi == 2 ? v2 : v3;
            float m = (gB[h * 16 + g] == myc) ? 1.0f : 0.0f;
            T += s;
            P += m * ep;          Pv += m * vp;
            R += m * (s - ep);    Rv += m * (vs - vp);
            Q += (1.0f - m) * ep; Qv += (1.0f - m) * vp;
        }
        T += __shfl_xor_sync(0xffffffffu, T, 1);
        P += __shfl_xor_sync(0xffffffffu, P, 1);
        Q += __shfl_xor_sync(0xffffffffu, Q, 1);
        R += __shfl_xor_sync(0xffffffffu, R, 1);
        Pv += __shfl_xor_sync(0xffffffffu, Pv, 1);
        Qv += __shfl_xor_sync(0xffffffffu, Qv, 1);
        Rv += __shfl_xor_sync(0xffffffffu, Rv, 1);
        if (h == 0) {
            float* d = g_rows + (size_t)(bm + a) * 8;
            atomicAdd(d + 0, T);  atomicAdd(d + 1, P);  atomicAdd(d + 2, Q);
            atomicAdd(d + 3, R);  atomicAdd(d + 4, Pv); atomicAdd(d + 5, Qv);
            atomicAdd(d + 6, Rv);
        }
    }

    // ---- col pass (off-diagonal only) ----
    if (bm != bn) {
        const int c = tid >> 1, h = tid & 1;
        const int myc = gB[c >> 2], pi = c & 3;
        float T = 0.f, P = 0.f, Q = 0.f, R = 0.f, Pv = 0.f, Qv = 0.f, Rv = 0.f;
#pragma unroll
        for (int g = 0; g < 16; g++) {
            const int j0 = h * 64 + g * 4;
            float v0 = (float)stgi[(j0 + 0) * LDG + c] * INV_Q2;
            float v1 = (float)stgi[(j0 + 1) * LDG + c] * INV_Q2;
            float v2 = (float)stgi[(j0 + 2) * LDG + c] * INV_Q2;
            float v3 = (float)stgi[(j0 + 3) * LDG + c] * INV_Q2;
            float e0 = __expf(v0), e1 = __expf(v1), e2 = __expf(v2), e3 = __expf(v3);
            float s = (e0 + e1) + (e2 + e3);
            float vs = (v0 + v1) + (v2 + v3);
            float ep = pi == 0 ? e0 : pi == 1 ? e1 : pi == 2 ? e2 : e3;
            float vp = pi == 0 ? v0 : pi == 1 ? v1 : pi == 2 ? v2 : v3;
            float m = (gA[h * 16 + g] == myc) ? 1.0f : 0.0f;
            T += s;
            P += m * ep;          Pv += m * vp;
            R += m * (s - ep);    Rv += m * (vs - vp);
            Q += (1.0f - m) * ep; Qv += (1.0f - m) * vp;
        }
        T += __shfl_xor_sync(0xffffffffu, T, 1);
        P += __shfl_xor_sync(0xffffffffu, P, 1);
        Q += __shfl_xor_sync(0xffffffffu, Q, 1);
        R += __shfl_xor_sync(0xffffffffu, R, 1);
        Pv += __shfl_xor_sync(0xffffffffu, Pv, 1);
        Qv += __shfl_xor_sync(0xffffffffu, Qv, 1);
        Rv += __shfl_xor_sync(0xffffffffu, Rv, 1);
        if (h == 0) {
            float* d = g_rows + (size_t)(bn + c) * 8;
            atomicAdd(d + 0, T);  atomicAdd(d + 1, P);  atomicAdd(d + 2, Q);
            atomicAdd(d + 3, R);  atomicAdd(d + 4, Pv); atomicAdd(d + 5, Qv);
            atomicAdd(d + 6, Rv);
        }
    }
}

// ---------------- assemble (32 blocks) + last-block finalize ----------------
// E1 = T-P; E2 = T-P-Q-R.  x = e^{-v}E >= ~700:
// sum_pos log1p(e^{-v}E) = n*logE - sum(v) + sum(e^v)/E
__global__ void assemble_kernel(float* out) {
    const int i = blockIdx.x * 256 + threadIdx.x;      // 8192 threads over 32 blocks
    const float* b = g_rows + (size_t)i * 8;
    float T = b[0], P = b[1], Q = b[2], R = b[3], Pv = b[4], Qv = b[5], Rv = b[6];
    float E1 = T - P;
    float E2 = E1 - Q - R;
    float ct = (float)g_chist[g_tcls[i >> 2]];
    float c = ct * __logf(E1) - Pv + P / E1
            + (2048.0f + 2.0f * ct) * __logf(E2) - (Qv + Rv) + (Q + R) / E2;
    double d = (double)c;
#pragma unroll
    for (int o = 16; o > 0; o >>= 1) d += __shfl_xor_sync(0xffffffffu, d, o);
    if ((threadIdx.x & 31) == 0) atomicAdd(&g_np, d);
    __syncthreads();
    if (threadIdx.x == 0) {
        __threadfence();
        unsigned done = atomicAdd(&g_done, 1u);
        if (done == 31u) {                             // last block finalizes
            __threadfence();
            double np = atomicAdd(&g_np, 0.0);         // ordered read
            double ce = g_ce;
            out[0] = (float)(ce / (double)BATCH + 0.5 * (np / (double)NR));
            g_done = 0u;
            g_ready = 0u;                              // reset for next replay
        }
    }
}

// ---------------- launch ----------------
extern "C" void kernel_launch(void* const* d_in, const int* in_sizes, int n_in,
                              void* d_out, int out_size) {
    const float* pred = nullptr;
    const float* x_part = nullptr;
    const unsigned int* traw = nullptr;
    for (int i = 0; i < n_in; i++) {
        if (in_sizes[i] == BATCH * NCLS)      pred   = (const float*)d_in[i];
        else if (in_sizes[i] == NR * DD)      x_part = (const float*)d_in[i];
        else if (in_sizes[i] == BATCH)        traw   = (const unsigned int*)d_in[i];
    }
    float* out = (float*)d_out;

    cudaFuncSetAttribute(gemm_fused_kernel, cudaFuncAttributeMaxDynamicSharedMemorySize,
                         GEMM_SMEM);

    norm_ce_kernel<<<NC_GRID, 256>>>(x_part, pred, traw);
    gemm_fused_kernel<<<NTILES, 256, GEMM_SMEM>>>();
    assemble_kernel<<<32, 256>>>(out);
}

// round 17
// speedup vs baseline: 1.1410x; 1.0038x over previous
#include <cuda_runtime.h>
#include <cuda_bf16.h>
#include <mma.h>
#include <cstdint>
#include <math.h>

using namespace nvcuda;

#define NR 8192
#define DD 512
#define BATCH 2048
#define NCLS 200

// ---------------- scratch (__device__ globals, no allocation) ----------------
__device__ signed char g_q[(size_t)NR * DD];     // quantized normalized features (4 MB)
__device__ float g_rows[(size_t)NR * 8];         // per-row {T,P,Q,R,Pv,Qv,Rv,pad} (256 KB)
__device__ int g_chist[NCLS];
__device__ double g_ce;
__device__ double g_np;
__device__ unsigned g_done;
__device__ unsigned char g_tcls[BATCH];

// ---------------- fused decode + normalize(+quantize) + zeroing ----------------
// block 0: decode targets + histogram; blocks 1..256: 32 rows each (4 rows/warp);
// last 16: zero g_rows.  (CE moved to the assemble kernel — off the critical path.)
#define NORM_BLKS (NR / 32)         // 256
#define ZBLK 16
#define NC_GRID (1 + NORM_BLKS + ZBLK)

__global__ void __launch_bounds__(256) norm_kernel(const float* __restrict__ x,
                                                   const unsigned int* __restrict__ traw) {
    const int b = blockIdx.x;
    const int tid = threadIdx.x;
    const int w = tid >> 5, lane = tid & 31;

    if (b == 0) {
        __shared__ int hist[NCLS];
        if (tid == 0) { g_ce = 0.0; g_np = 0.0; g_done = 0u; }
        for (int c = tid; c < NCLS; c += 256) hist[c] = 0;
        __syncthreads();
        int nz = 0;
        for (int i = tid; i < BATCH / 2; i += 256)
            if (traw[2 * i + 1] != 0u) nz = 1;
        if (__syncthreads_or(nz)) {           // int32 layout
            for (int i = tid; i < BATCH; i += 256) {
                unsigned char c = (unsigned char)traw[i];
                g_tcls[i] = c;
                atomicAdd(&hist[c], 1);
            }
        } else {                              // little-endian int64 layout
            for (int i = tid; i < BATCH; i += 256) {
                unsigned char c = (unsigned char)traw[2 * i];
                g_tcls[i] = c;
                atomicAdd(&hist[c], 1);
            }
        }
        __syncthreads();
        for (int c = tid; c < NCLS; c += 256) g_chist[c] = hist[c];
    } else if (b <= NORM_BLKS) {
        // 4 rows per warp: 16 independent float4 loads in flight
        const int row0 = (b - 1) * 32 + w * 4;
        float4 v[4][4];
        float s[4] = {0.f, 0.f, 0.f, 0.f};
#pragma unroll
        for (int rr = 0; rr < 4; rr++) {
            const float4* xr = (const float4*)(x + (size_t)(row0 + rr) * DD);
#pragma unroll
            for (int k = 0; k < 4; k++) v[rr][k] = xr[lane + 32 * k];
        }
#pragma unroll
        for (int rr = 0; rr < 4; rr++)
#pragma unroll
            for (int k = 0; k < 4; k++)
                s[rr] += v[rr][k].x * v[rr][k].x + v[rr][k].y * v[rr][k].y
                       + v[rr][k].z * v[rr][k].z + v[rr][k].w * v[rr][k].w;
#pragma unroll
        for (int o = 16; o > 0; o >>= 1)
#pragma unroll
            for (int rr = 0; rr < 4; rr++) s[rr] += __shfl_xor_sync(0xffffffffu, s[rr], o);
#pragma unroll
        for (int rr = 0; rr < 4; rr++) {
            const float inv = 127.0f / fmaxf(sqrtf(s[rr]), 1e-12f);
            char4* qr = (char4*)(g_q + (size_t)(row0 + rr) * DD);
#pragma unroll
            for (int k = 0; k < 4; k++) {
                char4 q;
                q.x = (signed char)__float2int_rn(v[rr][k].x * inv);
                q.y = (signed char)__float2int_rn(v[rr][k].y * inv);
                q.z = (signed char)__float2int_rn(v[rr][k].z * inv);
                q.w = (signed char)__float2int_rn(v[rr][k].w * inv);
                qr[lane + 32 * k] = q;
            }
        }
    } else {
        const int z = b - 1 - NORM_BLKS;
        float4* dst = (float4*)(g_rows) + (size_t)z * (NR * 8 / 4 / ZBLK);
        for (int i = tid; i < NR * 8 / 4 / ZBLK; i += 256)
            dst[i] = make_float4(0.f, 0.f, 0.f, 0.f);
    }
}

// ---------------- fused symmetric int8 GEMM + masked reductions ----------------
__device__ __forceinline__ void cp_async16(void* smem_dst, const void* gmem_src) {
    unsigned s = (unsigned)__cvta_generic_to_shared(smem_dst);
    asm volatile("cp.async.cg.shared.global [%0], [%1], 16;\n" :: "r"(s), "l"(gmem_src));
}

#define LDSB 80         // int8 row stride bytes: 64 + 16 pad (conflict-free LDSM)
#define LDG 132         // staging row stride (int32 elems)
#define STG_ELEMS (128 * LDSB)           // per-tensor per-stage bytes
#define STAGE_ELEMS (2 * STG_ELEMS)      // A+B per stage (20480 B)
#define NSTAGE 4
#define GEMM_SMEM (NSTAGE * STAGE_ELEMS) // 81920 B >= staging 67584 B
#define INV_Q2 (1.0f / 16129.0f)         // 1/127^2
#define NTILES 2080

__global__ void __launch_bounds__(256, 2) gemm_fused_kernel() {
    extern __shared__ char dsm[];
    signed char* sm = (signed char*)dsm;              // [4][A:128*80 | B:128*80]
    int* stgi = (int*)dsm;                            // 128*LDG int32 (reused)
    __shared__ unsigned char gA[32], gB[32];          // per-group (4 rows) class codes

    constexpr int NKIT = DD / 64;                     // 8 K-iterations

    // triangular tile decode: blockIdx.x in [0, 2080)
    int idx = blockIdx.x;
    int r = 0;
    while (idx >= 64 - r) { idx -= 64 - r; r++; }
    const int bm = r * 128;
    const int bn = (r + idx) * 128;

    const int tid = threadIdx.x;
    const int warp = tid >> 5;
    const int wm = (warp & 3) * 32;
    const int wn = (warp >> 2) * 64;

    // prefetch class bytes early (consumed after the K loop)
    if (tid < 32) gA[tid] = g_tcls[(bm >> 2) + tid];
    else if (tid < 64) gB[tid - 32] = g_tcls[(bn >> 2) + (tid - 32)];

    auto load_stage = [&](int k0, int s) {
        signed char* As = sm + s * STAGE_ELEMS;
        signed char* Bs = As + STG_ELEMS;
#pragma unroll
        for (int it = 0; it < 2; it++) {
            int c = it * 256 + tid;                   // 512 chunks of 16B per tensor
            int row = c >> 2;
            int col = (c & 3) * 16;
            cp_async16(&As[row * LDSB + col], g_q + (size_t)(bm + row) * DD + k0 * 64 + col);
            cp_async16(&Bs[row * LDSB + col], g_q + (size_t)(bn + row) * DD + k0 * 64 + col);
        }
    };

    wmma::fragment<wmma::accumulator, 16, 16, 16, int> acc[2][4];
#pragma unroll
    for (int i = 0; i < 2; i++)
#pragma unroll
        for (int j = 0; j < 4; j++) wmma::fill_fragment(acc[i][j], 0);

    load_stage(0, 0);
    asm volatile("cp.async.commit_group;\n");
    load_stage(1, 1);
    asm volatile("cp.async.commit_group;\n");
    load_stage(2, 2);
    asm volatile("cp.async.commit_group;\n");

    for (int k0 = 0; k0 < NKIT; k0++) {
        asm volatile("cp.async.wait_group 2;\n");      // stage k0 landed
        __syncthreads();                               // all warps done reading (k0-1)%4
        if (k0 + 3 < NKIT) load_stage(k0 + 3, (k0 + 3) & 3);
        asm volatile("cp.async.commit_group;\n");      // always commit (count alignment)

        const int s = k0 & 3;
        const signed char* As = sm + s * STAGE_ELEMS;
        const signed char* Bs = As + STG_ELEMS;

        // fragment double-buffer across kk: load kk+1 while MMA kk
        wmma::fragment<wmma::matrix_a, 16, 16, 16, signed char, wmma::row_major> fa[2][2];
        wmma::fragment<wmma::matrix_b, 16, 16, 16, signed char, wmma::col_major> fb[2][4];
#pragma unroll
        for (int i = 0; i < 2; i++)
            wmma::load_matrix_sync(fa[0][i], &As[(wm + i * 16) * LDSB], LDSB);
#pragma unroll
        for (int j = 0; j < 4; j++)
            wmma::load_matrix_sync(fb[0][j], &Bs[(wn + j * 16) * LDSB], LDSB);
#pragma unroll
        for (int kk = 0; kk < 4; kk++) {
            const int cur = kk & 1, nxt = cur ^ 1;
            if (kk < 3) {
#pragma unroll
                for (int i = 0; i < 2; i++)
                    wmma::load_matrix_sync(fa[nxt][i],
                                           &As[(wm + i * 16) * LDSB + (kk + 1) * 16], LDSB);
#pragma unroll
                for (int j = 0; j < 4; j++)
                    wmma::load_matrix_sync(fb[nxt][j],
                                           &Bs[(wn + j * 16) * LDSB + (kk + 1) * 16], LDSB);
            }
#pragma unroll
            for (int i = 0; i < 2; i++)
#pragma unroll
                for (int j = 0; j < 4; j++)
                    wmma::mma_sync(acc[i][j], fa[cur][i], fb[cur][j], acc[i][j]);
        }
    }
    __syncthreads();                                   // before reusing smem as staging

    // stage int32 tile in smem
#pragma unroll
    for (int i = 0; i < 2; i++)
#pragma unroll
        for (int j = 0; j < 4; j++)
            wmma::store_matrix_sync(stgi + (size_t)(wm + i * 16) * LDG + wn + j * 16,
                                    acc[i][j], LDG, wmma::mem_row_major);
    __syncthreads();

    // ---- row pass: 2 threads per anchor row (bm+a) ----
    {
        const int a = tid >> 1, h = tid & 1;
        const int myc = gA[a >> 2], pi = a & 3;
        float T = 0.f, P = 0.f, Q = 0.f, R = 0.f, Pv = 0.f, Qv = 0.f, Rv = 0.f;
        const int4* rp = (const int4*)(stgi + (size_t)a * LDG + h * 64);
#pragma unroll
        for (int g = 0; g < 16; g++) {
            int4 q4 = rp[g];
            float v0 = (float)q4.x * INV_Q2, v1 = (float)q4.y * INV_Q2;
            float v2 = (float)q4.z * INV_Q2, v3 = (float)q4.w * INV_Q2;
            float e0 = __expf(v0), e1 = __expf(v1), e2 = __expf(v2), e3 = __expf(v3);
            float s = (e0 + e1) + (e2 + e3);
            float vs = (v0 + v1) + (v2 + v3);
            float ep = pi == 0 ? e0 : pi == 1 ? e1 : pi == 2 ? e2 : e3;
            float vp = pi == 0 ? v0 : pi == 1 ? v1 : pi == 2 ? v2 : v3;
            float m = (gB[h * 16 + g] == myc) ? 1.0f : 0.0f;
            T += s;
            P += m * ep;          Pv += m * vp;
            R += m * (s - ep);    Rv += m * (vs - vp);
            Q += (1.0f - m) * ep; Qv += (1.0f - m) * vp;
        }
        T += __shfl_xor_sync(0xffffffffu, T, 1);
        P += __shfl_xor_sync(0xffffffffu, P, 1);
        Q += __shfl_xor_sync(0xffffffffu, Q, 1);
        R += __shfl_xor_sync(0xffffffffu, R, 1);
        Pv += __shfl_xor_sync(0xffffffffu, Pv, 1);
        Qv += __shfl_xor_sync(0xffffffffu, Qv, 1);
        Rv += __shfl_xor_sync(0xffffffffu, Rv, 1);
        if (h == 0) {
            float* d = g_rows + (size_t)(bm + a) * 8;
            atomicAdd(d + 0, T);  atomicAdd(d + 1, P);  atomicAdd(d + 2, Q);
            atomicAdd(d + 3, R);  atomicAdd(d + 4, Pv); atomicAdd(d + 5, Qv);
            atomicAdd(d + 6, Rv);
        }
    }

    // ---- col pass (off-diagonal only) ----
    if (bm != bn) {
        const int c = tid >> 1, h = tid & 1;
        const int myc = gB[c >> 2], pi = c & 3;
        float T = 0.f, P = 0.f, Q = 0.f, R = 0.f, Pv = 0.f, Qv = 0.f, Rv = 0.f;
#pragma unroll
        for (int g = 0; g < 16; g++) {
            const int j0 = h * 64 + g * 4;
            float v0 = (float)stgi[(j0 + 0) * LDG + c] * INV_Q2;
            float v1 = (float)stgi[(j0 + 1) * LDG + c] * INV_Q2;
            float v2 = (float)stgi[(j0 + 2) * LDG + c] * INV_Q2;
            float v3 = (float)stgi[(j0 + 3) * LDG + c] * INV_Q2;
            float e0 = __expf(v0), e1 = __expf(v1), e2 = __expf(v2), e3 = __expf(v3);
            float s = (e0 + e1) + (e2 + e3);
            float vs = (v0 + v1) + (v2 + v3);
            float ep = pi == 0 ? e0 : pi == 1 ? e1 : pi == 2 ? e2 : e3;
            float vp = pi == 0 ? v0 : pi == 1 ? v1 : pi == 2 ? v2 : v3;
            float m = (gA[h * 16 + g] == myc) ? 1.0f : 0.0f;
            T += s;
            P += m * ep;          Pv += m * vp;
            R += m * (s - ep);    Rv += m * (vs - vp);
            Q += (1.0f - m) * ep; Qv += (1.0f - m) * vp;
        }
        T += __shfl_xor_sync(0xffffffffu, T, 1);
        P += __shfl_xor_sync(0xffffffffu, P, 1);
        Q += __shfl_xor_sync(0xffffffffu, Q, 1);
        R += __shfl_xor_sync(0xffffffffu, R, 1);
        Pv += __shfl_xor_sync(0xffffffffu, Pv, 1);
        Qv += __shfl_xor_sync(0xffffffffu, Qv, 1);
        Rv += __shfl_xor_sync(0xffffffffu, Rv, 1);
        if (h == 0) {
            float* d = g_rows + (size_t)(bn + c) * 8;
            atomicAdd(d + 0, T);  atomicAdd(d + 1, P);  atomicAdd(d + 2, Q);
            atomicAdd(d + 3, R);  atomicAdd(d + 4, Pv); atomicAdd(d + 5, Qv);
            atomicAdd(d + 6, Rv);
        }
    }
}

// ---------------- assemble (32 blocks) + CE (128 blocks) + last-block finalize ----------------
// blocks 0..31: row assembly. E1=T-P; E2=E1-Q-R; x=e^{-v}E >= ~700:
//   sum_pos log1p(e^{-v}E) = n*logE - sum(v) + sum(e^v)/E
// blocks 32..159: CE label smoothing, 2 samples per warp.
#define ASM_BLKS 32
#define CE_BLKS (BATCH / 16)        // 128
#define AF_GRID (ASM_BLKS + CE_BLKS)

__global__ void __launch_bounds__(256) assemble_ce_kernel(float* out,
                                                          const float* __restrict__ pred) {
    const int b = blockIdx.x;
    const int tid = threadIdx.x;
    const int w = tid >> 5, lane = tid & 31;

    if (b < ASM_BLKS) {
        const int i = b * 256 + tid;                   // 8192 rows over 32 blocks
        const float* bp = g_rows + (size_t)i * 8;
        float T = bp[0], P = bp[1], Q = bp[2], R = bp[3], Pv = bp[4], Qv = bp[5], Rv = bp[6];
        float E1 = T - P;
        float E2 = E1 - Q - R;
        float ct = (float)g_chist[g_tcls[i >> 2]];
        float c = ct * __logf(E1) - Pv + P / E1
                + (2048.0f + 2.0f * ct) * __logf(E2) - (Qv + Rv) + (Q + R) / E2;
        double d = (double)c;
#pragma unroll
        for (int o = 16; o > 0; o >>= 1) d += __shfl_xor_sync(0xffffffffu, d, o);
        if (lane == 0) atomicAdd(&g_np, d);
    } else {
        // CE: 2 samples per warp
        const int i0 = (b - ASM_BLKS) * 16 + w * 2;
        const float* p0 = pred + (size_t)i0 * NCLS;
        const float* p1 = pred + (size_t)(i0 + 1) * NCLS;
        float pv0[7], pv1[7];
#pragma unroll
        for (int k = 0; k < 7; k++) {
            int c = lane + 32 * k;
            pv0[k] = (c < NCLS) ? p0[c] : -3.0e38f;
            pv1[k] = (c < NCLS) ? p1[c] : -3.0e38f;
        }
        float m0 = -3.0e38f, m1 = -3.0e38f, sl0 = 0.0f, sl1 = 0.0f;
#pragma unroll
        for (int k = 0; k < 7; k++) {
            m0 = fmaxf(m0, pv0[k]);
            m1 = fmaxf(m1, pv1[k]);
            if (lane + 32 * k < NCLS) { sl0 += pv0[k]; sl1 += pv1[k]; }
        }
#pragma unroll
        for (int o = 16; o > 0; o >>= 1) {
            m0 = fmaxf(m0, __shfl_xor_sync(0xffffffffu, m0, o));
            m1 = fmaxf(m1, __shfl_xor_sync(0xffffffffu, m1, o));
            sl0 += __shfl_xor_sync(0xffffffffu, sl0, o);
            sl1 += __shfl_xor_sync(0xffffffffu, sl1, o);
        }
        float se0 = 0.0f, se1 = 0.0f;
#pragma unroll
        for (int k = 0; k < 7; k++) {
            if (lane + 32 * k < NCLS) {
                se0 += __expf(pv0[k] - m0);
                se1 += __expf(pv1[k] - m1);
            }
        }
#pragma unroll
        for (int o = 16; o > 0; o >>= 1) {
            se0 += __shfl_xor_sync(0xffffffffu, se0, o);
            se1 += __shfl_xor_sync(0xffffffffu, se1, o);
        }
        if (lane == 0) {
            float lse0 = m0 + __logf(se0);
            float lse1 = m1 + __logf(se1);
            int t0 = (int)g_tcls[i0], t1 = (int)g_tcls[i0 + 1];
            float loss = 0.9f * (lse0 - p0[t0]) + 0.1f * (lse0 - sl0 / (float)NCLS)
                       + 0.9f * (lse1 - p1[t1]) + 0.1f * (lse1 - sl1 / (float)NCLS);
            atomicAdd(&g_ce, (double)loss);
        }
    }

    __syncthreads();
    if (tid == 0) {
        __threadfence();
        unsigned done = atomicAdd(&g_done, 1u);
        if (done == AF_GRID - 1u) {                    // last block finalizes
            __threadfence();
            double np = atomicAdd(&g_np, 0.0);         // ordered reads
            double ce = atomicAdd(&g_ce, 0.0);
            out[0] = (float)(ce / (double)BATCH + 0.5 * (np / (double)NR));
            g_done = 0u;                               // reset for next replay
        }
    }
}

// ---------------- launch ----------------
extern "C" void kernel_launch(void* const* d_in, const int* in_sizes, int n_in,
                              void* d_out, int out_size) {
    const float* pred = nullptr;
    const float* x_part = nullptr;
    const unsigned int* traw = nullptr;
    for (int i = 0; i < n_in; i++) {
        if (in_sizes[i] == BATCH * NCLS)      pred   = (const float*)d_in[i];
        else if (in_sizes[i] == NR * DD)      x_part = (const float*)d_in[i];
        else if (in_sizes[i] == BATCH)        traw   = (const unsigned int*)d_in[i];
    }
    float* out = (float*)d_out;

    cudaFuncSetAttribute(gemm_fused_kernel, cudaFuncAttributeMaxDynamicSharedMemorySize,
                         GEMM_SMEM);

    norm_kernel<<<NC_GRID, 256>>>(x_part, traw);
    gemm_fused_kernel<<<NTILES, 256, GEMM_SMEM>>>();
    assemble_ce_kernel<<<AF_GRID, 256>>>(out, pred);
}